// round 11
// baseline (speedup 1.0000x reference)
#include <cuda_runtime.h>

#define B_    4
#define N_    10000
#define E_    160000
#define NB_   (B_*N_)
#define HIST_ 8
#define PRED_ 12
#define FT_   20     // HIST+PRED
#define HID_  64

// ---------------- scratch (static device globals; no allocation) ----------------
__device__ float4 g_Psrc[NB_*8];     // (B*N, 32) per-node src projection
__device__ float4 g_Ptgt[NB_*8];     // (B*N, 32) per-node tgt projection
__device__ float4 g_Ce[E_*8];        // (E, 32) time-invariant edge const (ean@W + b1)
__device__ float2 g_ec[E_];          // (3cos(cd)/dist, 3sin(cd)/dist) per edge
__device__ float2 g_wind[NB_];       // (speed*cos(wd), speed*sin(wd)) per node
__device__ float4 g_agg[NB_*8];      // (B*N, 32) padded aggregation, node-major
__device__ float  g_hnT[HID_*NB_];   // GRU hidden, TRANSPOSED [u][node]
__device__ float  g_xn[NB_];         // current pm25 estimate
__device__ float  g_stats[4];        // mean0, inv_std0, mean1, inv_std1
__device__ int    g_idx32 = 0;       // 1 if edge_index is int32

__device__ __forceinline__ float sigm(float x){
    return __fdividef(1.f, 1.f + __expf(-x));
}
__device__ __forceinline__ float tanh_fast(float x){
    return fmaf(2.f, sigm(2.f*x), -1.f);
}

// ---------------- edge_index dtype detection ----------------
__global__ void k_detect(const unsigned* __restrict__ w){
    __shared__ int any;
    if (threadIdx.x==0) any = 0;
    __syncthreads();
    int nz = 0;
    for (int i = 2*(blockIdx.x*blockDim.x + threadIdx.x) + 1; i < 2*E_; i += 2*gridDim.x*blockDim.x)
        nz |= (w[i] != 0u);
    if (nz) any = 1;
    __syncthreads();
    if (threadIdx.x==0 && any) g_idx32 = 1;
}

// ---------------- edge_attr mean/std (ddof=1), one CTA ----------------
__global__ void k_stats(const float* __restrict__ ea){
    __shared__ float4 sh[32];
    float s0=0.f,q0=0.f,s1=0.f,q1=0.f;
    const float2* e2 = (const float2*)ea;
    for (int i=threadIdx.x; i<E_; i+=1024){
        float2 v = e2[i];
        s0+=v.x; q0+=v.x*v.x; s1+=v.y; q1+=v.y*v.y;
    }
    #pragma unroll
    for (int o=16;o>0;o>>=1){
        s0+=__shfl_down_sync(0xffffffffu,s0,o);
        q0+=__shfl_down_sync(0xffffffffu,q0,o);
        s1+=__shfl_down_sync(0xffffffffu,s1,o);
        q1+=__shfl_down_sync(0xffffffffu,q1,o);
    }
    int w=threadIdx.x>>5, l=threadIdx.x&31;
    if (l==0) sh[w]=make_float4(s0,q0,s1,q1);
    __syncthreads();
    if (w==0){
        float4 v = sh[l];
        s0=v.x; q0=v.y; s1=v.z; q1=v.w;
        #pragma unroll
        for (int o=16;o>0;o>>=1){
            s0+=__shfl_down_sync(0xffffffffu,s0,o);
            q0+=__shfl_down_sync(0xffffffffu,q0,o);
            s1+=__shfl_down_sync(0xffffffffu,s1,o);
            q1+=__shfl_down_sync(0xffffffffu,q1,o);
        }
        if (l==0){
            float m0=s0/(float)E_, m1=s1/(float)E_;
            float v0=fmaxf((q0-(float)E_*m0*m0)/(float)(E_-1),0.f);
            float v1=fmaxf((q1-(float)E_*m1*m1)/(float)(E_-1),0.f);
            g_stats[0]=m0; g_stats[1]=__fdividef(1.f,fmaxf(sqrtf(v0),1e-6f));
            g_stats[2]=m1; g_stats[3]=__fdividef(1.f,fmaxf(sqrtf(v1),1e-6f));
        }
    }
}

// ---------------- per-node pre-pass body (t=0 path in k_setup) ----------------
__device__ __forceinline__ void node_pre_body(
    int i, const float* __restrict__ feat, const float* s_w1,
    const float* __restrict__ wm, const float* __restrict__ ws, int t, bool zero_agg)
{
    int b = i / N_, n = i % N_;
    float x[9];
    x[0] = g_xn[i];
    const float* f = feat + ((size_t)(b*FT_ + HIST_ + t)*N_ + n)*8;
    #pragma unroll
    for (int k=0;k<8;k++) x[1+k]=f[k];
    float ws0 = fmaxf(__ldg(&ws[0]),1e-6f), ws1 = fmaxf(__ldg(&ws[1]),1e-6f);
    float w0 = fmaxf(x[7]*ws0 + __ldg(&wm[0]), 0.f);
    float wd = (x[8]*ws1 + __ldg(&wm[1])) * 0.017453292519943295f;
    float sw, cw;
    __sincosf(wd, &sw, &cw);
    g_wind[i] = make_float2(w0*cw, w0*sw);
    float ps[32], pt[32];
    #pragma unroll
    for (int j=0;j<32;j++){ ps[j]=0.f; pt[j]=0.f; }
    #pragma unroll
    for (int k=0;k<9;k++){
        float xv = x[k];
        #pragma unroll
        for (int j=0;j<32;j++){
            ps[j] = fmaf(xv, s_w1[k*32+j],     ps[j]);
            pt[j] = fmaf(xv, s_w1[(9+k)*32+j], pt[j]);
        }
    }
    float4* Pd = &g_Psrc[i*8];
    float4* Td = &g_Ptgt[i*8];
    #pragma unroll
    for (int q=0;q<8;q++){
        Pd[q]=make_float4(ps[4*q],ps[4*q+1],ps[4*q+2],ps[4*q+3]);
        Td[q]=make_float4(pt[4*q],pt[4*q+1],pt[4*q+2],pt[4*q+3]);
    }
    if (zero_agg){
        float4* Ad = &g_agg[i*8];
        #pragma unroll
        for (int q=0;q<8;q++) Ad[q]=make_float4(0.f,0.f,0.f,0.f);
    }
}

// ---------------- fused setup: ce (blocks 0..624) + init/node_pre t=0 ----------
#define CE_BLOCKS 625
__global__ __launch_bounds__(256) void k_setup(
    const float* __restrict__ pm, const float* __restrict__ feat,
    const float* __restrict__ ea, const float* __restrict__ w1,
    const float* __restrict__ b1,
    const float* __restrict__ wm, const float* __restrict__ ws)
{
    if (blockIdx.x < CE_BLOCKS){
        int e = blockIdx.x*256 + threadIdx.x;
        if (e >= E_) return;
        float m0=g_stats[0], i0=g_stats[1], m1=g_stats[2], i1=g_stats[3];
        float2 a = ((const float2*)ea)[e];
        float n0 = (a.x-m0)*i0, n1 = (a.y-m1)*i1;
        float4* dst = &g_Ce[e*8];
        #pragma unroll
        for (int q=0;q<8;q++){
            float v[4];
            #pragma unroll
            for (int l=0;l<4;l++){
                int j = 4*q+l;
                v[l] = __ldg(&b1[j]) + n0*__ldg(&w1[18*32+j]) + n1*__ldg(&w1[19*32+j]);
            }
            dst[q] = make_float4(v[0],v[1],v[2],v[3]);
        }
        float dist = fmaxf(a.x, 1e-3f);
        float inv3 = __fdividef(3.f, dist);
        g_ec[e] = make_float2(cosf(a.y)*inv3, sinf(a.y)*inv3);
    } else {
        __shared__ float s_w1[18*32];
        for (int p=threadIdx.x; p<18*32; p+=256) s_w1[p]=w1[p];
        __syncthreads();
        int i = (blockIdx.x - CE_BLOCKS)*256 + threadIdx.x;
        if (i >= NB_) return;
        #pragma unroll
        for (int u=0;u<HID_;u++) g_hnT[u*NB_ + i] = 0.f;
        int b = i / N_, n = i % N_;
        g_xn[i] = pm[(b*HIST_ + (HIST_-1))*N_ + n];
        node_pre_body(i, feat, s_w1, wm, ws, 0, true);
    }
}

// ---------------- edge MLP + scatter: 1 warp = 1 edge, row-per-lane -----------
// Lane r holds w2 row r in 32 registers (amortized over grid-stride loop).
// Layer1: lane computes h1 column `lane` (coalesced 128B gathers).
// h1 exchanged via 32B STS + 8 broadcast LDS.128; double-buffered, 1 syncwarp.
__global__ __launch_bounds__(256) void k_edge(
    const void* __restrict__ eiv, const float* __restrict__ w1,
    const float* __restrict__ w2, const float* __restrict__ b2)
{
    __shared__ float s_h1[8][2][32];
    int lane = threadIdx.x & 31;
    int wid  = threadIdx.x >> 5;

    float wreg[32];
    #pragma unroll
    for (int j=0;j<32;j++)
        wreg[j] = (lane < 30) ? __ldg(&w2[j*30 + lane]) : 0.f;
    float b2r = (lane < 30) ? __ldg(&b2[lane]) : 0.f;
    float w20 = __ldg(&w1[20*32 + lane]);

    int b = blockIdx.y;
    const int gw = gridDim.x * 8;
    const float* Ps = (const float*)g_Psrc;
    const float* Pt = (const float*)g_Ptgt;
    const float* Cc = (const float*)g_Ce;
    bool idx32 = (g_idx32 != 0);
    int buf = 0;

    for (int e = blockIdx.x*8 + wid; e < E_; e += gw, buf ^= 1){
        int s, tg;
        if (idx32){
            const int* ei = (const int*)eiv;
            s = __ldg(&ei[e]); tg = __ldg(&ei[E_+e]);
        } else {
            const long long* ei = (const long long*)eiv;
            s = (int)__ldg(&ei[e]); tg = (int)__ldg(&ei[E_+e]);
        }
        s  = min(max(s, 0), N_-1);
        tg = min(max(tg, 0), N_-1);
        int is = b*N_ + s, it = b*N_ + tg;

        float2 wn = g_wind[is];
        float2 ec = g_ec[e];
        float ew = fmaxf(fmaf(ec.x, wn.x, ec.y*wn.y), 0.f);

        float h1 = sigm(Ps[(size_t)is*32 + lane] + Pt[(size_t)it*32 + lane]
                        + Cc[(size_t)e*32 + lane] + ew*w20);
        s_h1[wid][buf][lane] = h1;
        __syncwarp();

        const float4* H = (const float4*)s_h1[wid][buf];
        float a0 = b2r, a1 = 0.f, a2 = 0.f, a3 = 0.f;
        #pragma unroll
        for (int m=0;m<8;m+=4){
            float4 h0 = H[m+0], hA = H[m+1], hB = H[m+2], hC = H[m+3];
            a0 = fmaf(wreg[4*m+0], h0.x, fmaf(wreg[4*m+1], h0.y, fmaf(wreg[4*m+2], h0.z, fmaf(wreg[4*m+3], h0.w, a0))));
            a1 = fmaf(wreg[4*m+4], hA.x, fmaf(wreg[4*m+5], hA.y, fmaf(wreg[4*m+6], hA.z, fmaf(wreg[4*m+7], hA.w, a1))));
            a2 = fmaf(wreg[4*m+8], hB.x, fmaf(wreg[4*m+9], hB.y, fmaf(wreg[4*m+10],hB.z, fmaf(wreg[4*m+11],hB.w, a2))));
            a3 = fmaf(wreg[4*m+12],hC.x, fmaf(wreg[4*m+13],hC.y, fmaf(wreg[4*m+14],hC.z, fmaf(wreg[4*m+15],hC.w, a3))));
        }
        float o = sigm((a0+a1) + (a2+a3));
        if (lane < 30){
            atomicAdd((float*)&g_agg[it*8] + lane,  o);
            atomicAdd((float*)&g_agg[is*8] + lane, -o);
        }
    }
}

// ---------------- node MLP + GRU + FC + next-step projections, fused ----------
__global__ __launch_bounds__(128) void k_gru(
    const float* __restrict__ feat,
    const float* __restrict__ nw, const float* __restrict__ nb,
    const float* __restrict__ wi, const float* __restrict__ wh,
    const float* __restrict__ bi, const float* __restrict__ bh,
    const float* __restrict__ fw, const float* __restrict__ fb,
    const float* __restrict__ w1, const float* __restrict__ wm,
    const float* __restrict__ ws,
    float* __restrict__ out, int t)
{
    __shared__ float s_wh[192*64];  // 48KB (static limit)
    for (int p=threadIdx.x; p<192*64; p+=128) s_wh[p]=wh[p];
    __syncthreads();
    int i = blockIdx.x*128 + threadIdx.x;
    if (i >= NB_) return;
    int b = i / N_, n = i % N_;

    // --- node GNN output: sigmoid(agg @ n_w + n_b); zero agg for next step ---
    float ag[30];
    {
        float4* A = &g_agg[i*8];
        #pragma unroll
        for (int q=0;q<7;q++){
            float4 v = A[q];
            ag[4*q]=v.x; ag[4*q+1]=v.y; ag[4*q+2]=v.z; ag[4*q+3]=v.w;
        }
        float4 v = A[7]; ag[28]=v.x; ag[29]=v.y;
        #pragma unroll
        for (int q=0;q<8;q++) A[q]=make_float4(0.f,0.f,0.f,0.f);
    }
    float xc[22];
    #pragma unroll
    for (int c=0;c<13;c++){
        float acc = __ldg(&nb[c]);
        #pragma unroll
        for (int r=0;r<30;r++) acc = fmaf(ag[r], __ldg(&nw[r*13+c]), acc);
        xc[c] = sigm(acc);
    }
    xc[13] = g_xn[i];
    const float* f = feat + ((size_t)(b*FT_ + HIST_ + t)*N_ + n)*8;
    #pragma unroll
    for (int k=0;k<8;k++) xc[14+k]=f[k];

    // --- GRU: coalesced transposed state ---
    float h[64];
    #pragma unroll
    for (int u=0;u<64;u++) h[u] = g_hnT[u*NB_ + i];

    float fcacc = 0.f;
    #pragma unroll 2
    for (int u=0;u<64;u++){
        const float2* wr = (const float2*)(wi + (size_t)u*22);
        const float2* wz = (const float2*)(wi + (size_t)(64+u)*22);
        const float2* wn2= (const float2*)(wi + (size_t)(128+u)*22);
        float gr = __ldg(&bi[u]), gz = __ldg(&bi[64+u]), gn = __ldg(&bi[128+u]);
        #pragma unroll
        for (int k=0;k<11;k++){
            float2 a = __ldg(&wr[k]);  gr = fmaf(a.x,xc[2*k],fmaf(a.y,xc[2*k+1],gr));
            float2 c = __ldg(&wz[k]);  gz = fmaf(c.x,xc[2*k],fmaf(c.y,xc[2*k+1],gz));
            float2 d = __ldg(&wn2[k]); gn = fmaf(d.x,xc[2*k],fmaf(d.y,xc[2*k+1],gn));
        }
        float hr = __ldg(&bh[u]), hz = __ldg(&bh[64+u]), hv_n = __ldg(&bh[128+u]);
        const float4* whr = (const float4*)&s_wh[u*64];
        const float4* whz = (const float4*)&s_wh[(64+u)*64];
        const float4* whn = (const float4*)&s_wh[(128+u)*64];
        #pragma unroll
        for (int k=0;k<16;k++){
            float4 a = whr[k];
            hr = fmaf(a.x,h[4*k],fmaf(a.y,h[4*k+1],fmaf(a.z,h[4*k+2],fmaf(a.w,h[4*k+3],hr))));
            float4 c = whz[k];
            hz = fmaf(c.x,h[4*k],fmaf(c.y,h[4*k+1],fmaf(c.z,h[4*k+2],fmaf(c.w,h[4*k+3],hz))));
            float4 d = whn[k];
            hv_n = fmaf(d.x,h[4*k],fmaf(d.y,h[4*k+1],fmaf(d.z,h[4*k+2],fmaf(d.w,h[4*k+3],hv_n))));
        }
        float r = sigm(gr+hr), z = sigm(gz+hz);
        float nn = tanh_fast(gn + r*hv_n);
        float hv = (1.f-z)*nn + z*h[u];
        g_hnT[u*NB_ + i] = hv;         // coalesced store
        fcacc = fmaf(hv, __ldg(&fw[u]), fcacc);
    }
    float xn = fcacc + __ldg(&fb[0]);
    g_xn[i] = xn;
    out[(size_t)i*PRED_ + t] = xn;

    // --- fused node_pre for step t+1 ---
    if (t+1 < PRED_){
        float x[9];
        x[0] = xn;
        const float* f2 = feat + ((size_t)(b*FT_ + HIST_ + t+1)*N_ + n)*8;
        #pragma unroll
        for (int k=0;k<8;k++) x[1+k]=f2[k];
        float ws0 = fmaxf(__ldg(&ws[0]),1e-6f), ws1 = fmaxf(__ldg(&ws[1]),1e-6f);
        float w0 = fmaxf(x[7]*ws0 + __ldg(&wm[0]), 0.f);
        float wd = (x[8]*ws1 + __ldg(&wm[1])) * 0.017453292519943295f;
        float sw, cw;
        __sincosf(wd, &sw, &cw);
        g_wind[i] = make_float2(w0*cw, w0*sw);
        float ps[32], pt[32];
        #pragma unroll
        for (int j=0;j<32;j++){ ps[j]=0.f; pt[j]=0.f; }
        #pragma unroll
        for (int k=0;k<9;k++){
            float xv = x[k];
            #pragma unroll
            for (int j=0;j<32;j++){
                ps[j] = fmaf(xv, __ldg(&w1[k*32+j]),     ps[j]);
                pt[j] = fmaf(xv, __ldg(&w1[(9+k)*32+j]), pt[j]);
            }
        }
        float4* Pd = &g_Psrc[i*8];
        float4* Td = &g_Ptgt[i*8];
        #pragma unroll
        for (int q=0;q<8;q++){
            Pd[q]=make_float4(ps[4*q],ps[4*q+1],ps[4*q+2],ps[4*q+3]);
            Td[q]=make_float4(pt[4*q],pt[4*q+1],pt[4*q+2],pt[4*q+3]);
        }
    }
}

extern "C" void kernel_launch(void* const* d_in, const int* in_sizes, int n_in,
                              void* d_out, int out_size){
    const float* pm   = (const float*)d_in[0];
    const float* feat = (const float*)d_in[1];
    const float* ea   = (const float*)d_in[2];
    const float* wm   = (const float*)d_in[3];
    const float* ws   = (const float*)d_in[4];
    const float* ew1  = (const float*)d_in[5];
    const float* eb1  = (const float*)d_in[6];
    const float* ew2  = (const float*)d_in[7];
    const float* eb2  = (const float*)d_in[8];
    const float* nw   = (const float*)d_in[9];
    const float* nb   = (const float*)d_in[10];
    const float* wi   = (const float*)d_in[11];
    const float* wh   = (const float*)d_in[12];
    const float* bi   = (const float*)d_in[13];
    const float* bh   = (const float*)d_in[14];
    const float* fw   = (const float*)d_in[15];
    const float* fb   = (const float*)d_in[16];
    const void*  ei   = d_in[17];
    float* out = (float*)d_out;

    dim3 ge(256, B_);   // 256 CTAs x 8 warps, grid-stride over 160k edges
    k_detect<<<64,256>>>((const unsigned*)ei);
    k_stats<<<1,1024>>>(ea);
    k_setup<<<CE_BLOCKS + (NB_+255)/256, 256>>>(pm, feat, ea, ew1, eb1, wm, ws);
    for (int t=0;t<PRED_;t++){
        k_edge<<<ge,256>>>(ei, ew1, ew2, eb2);
        k_gru<<<(NB_+127)/128,128>>>(feat, nw, nb, wi, wh, bi, bh, fw, fb,
                                     ew1, wm, ws, out, t);
    }
    (void)in_sizes; (void)n_in; (void)out_size;
}

// round 12
// speedup vs baseline: 1.3196x; 1.3196x over previous
#include <cuda_runtime.h>

#define B_    4
#define N_    10000
#define E_    160000
#define NB_   (B_*N_)
#define HIST_ 8
#define PRED_ 12
#define FT_   20     // HIST+PRED
#define HID_  64

// ---------------- scratch (static device globals; no allocation) ----------------
__device__ float4 g_Psrc[NB_*8];     // (B*N, 32) per-node src projection
__device__ float4 g_Ptgt[NB_*8];     // (B*N, 32) per-node tgt projection
__device__ float4 g_Ce[E_*8];        // (E, 32) time-invariant edge const (ean@W + b1)
__device__ float2 g_ec[E_];          // (3cos(cd)/dist, 3sin(cd)/dist) per edge
__device__ float2 g_wind[NB_];       // (speed*cos(wd), speed*sin(wd)) per node
__device__ float4 g_agg[NB_*8];      // (B*N, 32) padded aggregation, node-major
__device__ float  g_hnT[HID_*NB_];   // GRU hidden, TRANSPOSED [u][node]
__device__ float  g_xn[NB_];         // current pm25 estimate
__device__ float  g_stats[4];        // mean0, inv_std0, mean1, inv_std1
__device__ int    g_idx32 = 0;       // 1 if edge_index is int32

__device__ __forceinline__ float sigm(float x){
    return __fdividef(1.f, 1.f + __expf(-x));
}
__device__ __forceinline__ float tanh_fast(float x){
    return fmaf(2.f, sigm(2.f*x), -1.f);
}
__device__ __forceinline__ void red4(float* p, float a, float b, float c, float d){
    asm volatile("red.global.add.v4.f32 [%0], {%1,%2,%3,%4};"
                 :: "l"(p), "f"(a), "f"(b), "f"(c), "f"(d) : "memory");
}

// ---------------- edge_index dtype detection ----------------
__global__ void k_detect(const unsigned* __restrict__ w){
    __shared__ int any;
    if (threadIdx.x==0) any = 0;
    __syncthreads();
    int nz = 0;
    for (int i = 2*(blockIdx.x*blockDim.x + threadIdx.x) + 1; i < 2*E_; i += 2*gridDim.x*blockDim.x)
        nz |= (w[i] != 0u);
    if (nz) any = 1;
    __syncthreads();
    if (threadIdx.x==0 && any) g_idx32 = 1;
}

// ---------------- edge_attr mean/std (ddof=1), one CTA ----------------
__global__ void k_stats(const float* __restrict__ ea){
    __shared__ float4 sh[32];
    float s0=0.f,q0=0.f,s1=0.f,q1=0.f;
    const float2* e2 = (const float2*)ea;
    for (int i=threadIdx.x; i<E_; i+=1024){
        float2 v = e2[i];
        s0+=v.x; q0+=v.x*v.x; s1+=v.y; q1+=v.y*v.y;
    }
    #pragma unroll
    for (int o=16;o>0;o>>=1){
        s0+=__shfl_down_sync(0xffffffffu,s0,o);
        q0+=__shfl_down_sync(0xffffffffu,q0,o);
        s1+=__shfl_down_sync(0xffffffffu,s1,o);
        q1+=__shfl_down_sync(0xffffffffu,q1,o);
    }
    int w=threadIdx.x>>5, l=threadIdx.x&31;
    if (l==0) sh[w]=make_float4(s0,q0,s1,q1);
    __syncthreads();
    if (w==0){
        float4 v = sh[l];
        s0=v.x; q0=v.y; s1=v.z; q1=v.w;
        #pragma unroll
        for (int o=16;o>0;o>>=1){
            s0+=__shfl_down_sync(0xffffffffu,s0,o);
            q0+=__shfl_down_sync(0xffffffffu,q0,o);
            s1+=__shfl_down_sync(0xffffffffu,s1,o);
            q1+=__shfl_down_sync(0xffffffffu,q1,o);
        }
        if (l==0){
            float m0=s0/(float)E_, m1=s1/(float)E_;
            float v0=fmaxf((q0-(float)E_*m0*m0)/(float)(E_-1),0.f);
            float v1=fmaxf((q1-(float)E_*m1*m1)/(float)(E_-1),0.f);
            g_stats[0]=m0; g_stats[1]=__fdividef(1.f,fmaxf(sqrtf(v0),1e-6f));
            g_stats[2]=m1; g_stats[3]=__fdividef(1.f,fmaxf(sqrtf(v1),1e-6f));
        }
    }
}

// ---------------- per-node pre-pass body (t=0 path in k_setup) ----------------
__device__ __forceinline__ void node_pre_body(
    int i, const float* __restrict__ feat, const float* s_w1,
    const float* __restrict__ wm, const float* __restrict__ ws, int t, bool zero_agg)
{
    int b = i / N_, n = i % N_;
    float x[9];
    x[0] = g_xn[i];
    const float* f = feat + ((size_t)(b*FT_ + HIST_ + t)*N_ + n)*8;
    #pragma unroll
    for (int k=0;k<8;k++) x[1+k]=f[k];
    float ws0 = fmaxf(__ldg(&ws[0]),1e-6f), ws1 = fmaxf(__ldg(&ws[1]),1e-6f);
    float w0 = fmaxf(x[7]*ws0 + __ldg(&wm[0]), 0.f);
    float wd = (x[8]*ws1 + __ldg(&wm[1])) * 0.017453292519943295f;
    float sw, cw;
    __sincosf(wd, &sw, &cw);
    g_wind[i] = make_float2(w0*cw, w0*sw);
    float ps[32], pt[32];
    #pragma unroll
    for (int j=0;j<32;j++){ ps[j]=0.f; pt[j]=0.f; }
    #pragma unroll
    for (int k=0;k<9;k++){
        float xv = x[k];
        #pragma unroll
        for (int j=0;j<32;j++){
            ps[j] = fmaf(xv, s_w1[k*32+j],     ps[j]);
            pt[j] = fmaf(xv, s_w1[(9+k)*32+j], pt[j]);
        }
    }
    float4* Pd = &g_Psrc[i*8];
    float4* Td = &g_Ptgt[i*8];
    #pragma unroll
    for (int q=0;q<8;q++){
        Pd[q]=make_float4(ps[4*q],ps[4*q+1],ps[4*q+2],ps[4*q+3]);
        Td[q]=make_float4(pt[4*q],pt[4*q+1],pt[4*q+2],pt[4*q+3]);
    }
    if (zero_agg){
        float4* Ad = &g_agg[i*8];
        #pragma unroll
        for (int q=0;q<8;q++) Ad[q]=make_float4(0.f,0.f,0.f,0.f);
    }
}

// ---------------- fused setup: ce (blocks 0..624) + init/node_pre t=0 ----------
#define CE_BLOCKS 625
__global__ __launch_bounds__(256) void k_setup(
    const float* __restrict__ pm, const float* __restrict__ feat,
    const float* __restrict__ ea, const float* __restrict__ w1,
    const float* __restrict__ b1,
    const float* __restrict__ wm, const float* __restrict__ ws)
{
    if (blockIdx.x < CE_BLOCKS){
        int e = blockIdx.x*256 + threadIdx.x;
        if (e >= E_) return;
        float m0=g_stats[0], i0=g_stats[1], m1=g_stats[2], i1=g_stats[3];
        float2 a = ((const float2*)ea)[e];
        float n0 = (a.x-m0)*i0, n1 = (a.y-m1)*i1;
        float4* dst = &g_Ce[e*8];
        #pragma unroll
        for (int q=0;q<8;q++){
            float v[4];
            #pragma unroll
            for (int l=0;l<4;l++){
                int j = 4*q+l;
                v[l] = __ldg(&b1[j]) + n0*__ldg(&w1[18*32+j]) + n1*__ldg(&w1[19*32+j]);
            }
            dst[q] = make_float4(v[0],v[1],v[2],v[3]);
        }
        float dist = fmaxf(a.x, 1e-3f);
        float inv3 = __fdividef(3.f, dist);
        g_ec[e] = make_float2(cosf(a.y)*inv3, sinf(a.y)*inv3);
    } else {
        __shared__ float s_w1[18*32];
        for (int p=threadIdx.x; p<18*32; p+=256) s_w1[p]=w1[p];
        __syncthreads();
        int i = (blockIdx.x - CE_BLOCKS)*256 + threadIdx.x;
        if (i >= NB_) return;
        #pragma unroll
        for (int u=0;u<HID_;u++) g_hnT[u*NB_ + i] = 0.f;
        int b = i / N_, n = i % N_;
        g_xn[i] = pm[(b*HIST_ + (HIST_-1))*N_ + n];
        node_pre_body(i, feat, s_w1, wm, ws, 0, true);
    }
}

// ---------------- edge MLP + scatter: 8 lanes/edge, 16 edges/warp -------------
// warp = 4 quads x 4 edges; lane (sub=lane>>3, q=lane&7) handles edge `sub` of
// each quad, rows 4q..4q+3. Weight float4s loaded once per m and applied to all
// 4 quads (4x amortization of shared-pipe traffic).
__global__ __launch_bounds__(256) void k_edge(
    const void* __restrict__ eiv,
    const float* __restrict__ w1, const float* __restrict__ w2,
    const float* __restrict__ b2)
{
    __shared__ float4 s_w2v[256];       // [m][l][q]: w2 rows r=4q+l, cols 4m..4m+3
    __shared__ float s_w20[32];
    __shared__ float s_b2[32];
    __shared__ float s_h1[8][4][4*36];  // [warp][quad][edge*36 + col]
    {
        int p = threadIdx.x;            // 256 threads fill 256 float4s
        int m = p>>5, l=(p>>3)&3, q=p&7;
        int r = 4*q + l;
        float4 w;
        if (r < 30){
            w.x = w2[(4*m+0)*30 + r];
            w.y = w2[(4*m+1)*30 + r];
            w.z = w2[(4*m+2)*30 + r];
            w.w = w2[(4*m+3)*30 + r];
        } else w = make_float4(0.f,0.f,0.f,0.f);
        s_w2v[p] = w;
        if (p < 32){
            s_w20[p] = w1[20*32 + p];
            s_b2[p]  = (p < 30) ? b2[p] : 0.f;
        }
    }
    __syncthreads();

    int lane = threadIdx.x & 31;
    int wid  = threadIdx.x >> 5;
    int sub  = lane >> 3;
    int q    = lane & 7;
    int base = (blockIdx.x*8 + wid)*16;
    int b    = blockIdx.y;
    bool idx32 = (g_idx32 != 0);

    int isv[4], itv[4];

    // ---- phase A: h1 for 4 quads (16 edges) ----
    #pragma unroll
    for (int bq=0; bq<4; bq++){
        int e = base + bq*4 + sub;
        int s, tg;
        if (idx32){
            const int* ei = (const int*)eiv;
            s = __ldg(&ei[e]); tg = __ldg(&ei[E_+e]);
        } else {
            const long long* ei = (const long long*)eiv;
            s = (int)__ldg(&ei[e]); tg = (int)__ldg(&ei[E_+e]);
        }
        s  = min(max(s, 0), N_-1);
        tg = min(max(tg, 0), N_-1);
        int is = b*N_ + s, it = b*N_ + tg;
        isv[bq] = is; itv[bq] = it;

        float2 wn = g_wind[is];
        float2 ec = g_ec[e];
        float ew = fmaxf(fmaf(ec.x, wn.x, ec.y*wn.y), 0.f);

        float4 u = g_Psrc[is*8 + q];
        float4 v = g_Ptgt[it*8 + q];
        float4 c = g_Ce[e*8 + q];
        float4 h;
        h.x = sigm(u.x+v.x+c.x + ew*s_w20[q*4+0]);
        h.y = sigm(u.y+v.y+c.y + ew*s_w20[q*4+1]);
        h.z = sigm(u.z+v.z+c.z + ew*s_w20[q*4+2]);
        h.w = sigm(u.w+v.w+c.w + ew*s_w20[q*4+3]);
        *(float4*)&s_h1[wid][bq][sub*36 + q*4] = h;
    }
    __syncwarp();

    // ---- phase B: layer2, weights loaded once per m, applied to 4 quads ----
    float acc[4][4];
    #pragma unroll
    for (int bq=0;bq<4;bq++){
        acc[bq][0]=s_b2[4*q+0]; acc[bq][1]=s_b2[4*q+1];
        acc[bq][2]=s_b2[4*q+2]; acc[bq][3]=s_b2[4*q+3];
    }
    #pragma unroll
    for (int m=0;m<8;m++){
        float4 w0 = s_w2v[(m*4+0)*8 + q];
        float4 w1v= s_w2v[(m*4+1)*8 + q];
        float4 w2v= s_w2v[(m*4+2)*8 + q];
        float4 w3 = s_w2v[(m*4+3)*8 + q];
        #pragma unroll
        for (int bq=0;bq<4;bq++){
            float4 hh = *(const float4*)&s_h1[wid][bq][sub*36 + m*4];
            acc[bq][0] = fmaf(w0.x,hh.x,fmaf(w0.y,hh.y,fmaf(w0.z,hh.z,fmaf(w0.w,hh.w,acc[bq][0]))));
            acc[bq][1] = fmaf(w1v.x,hh.x,fmaf(w1v.y,hh.y,fmaf(w1v.z,hh.z,fmaf(w1v.w,hh.w,acc[bq][1]))));
            acc[bq][2] = fmaf(w2v.x,hh.x,fmaf(w2v.y,hh.y,fmaf(w2v.z,hh.z,fmaf(w2v.w,hh.w,acc[bq][2]))));
            acc[bq][3] = fmaf(w3.x,hh.x,fmaf(w3.y,hh.y,fmaf(w3.z,hh.z,fmaf(w3.w,hh.w,acc[bq][3]))));
        }
    }

    // ---- epilogue: sigmoid + scatter ----
    #pragma unroll
    for (int bq=0;bq<4;bq++){
        float o0 = sigm(acc[bq][0]), o1 = sigm(acc[bq][1]);
        float o2 = sigm(acc[bq][2]), o3 = sigm(acc[bq][3]);
        float* at = (float*)&g_agg[itv[bq]*8] + 4*q;
        float* as = (float*)&g_agg[isv[bq]*8] + 4*q;
        red4(at,  o0,  o1,  o2,  o3);   // rows 30,31 are zero-weight pads, never read
        red4(as, -o0, -o1, -o2, -o3);
    }
}

// ---------------- node MLP + GRU + FC + next-step projections, fused ----------
__global__ __launch_bounds__(128) void k_gru(
    const float* __restrict__ feat,
    const float* __restrict__ nw, const float* __restrict__ nb,
    const float* __restrict__ wi, const float* __restrict__ wh,
    const float* __restrict__ bi, const float* __restrict__ bh,
    const float* __restrict__ fw, const float* __restrict__ fb,
    const float* __restrict__ w1, const float* __restrict__ wm,
    const float* __restrict__ ws,
    float* __restrict__ out, int t)
{
    __shared__ float s_wh[192*64];  // 48KB
    for (int p=threadIdx.x; p<192*64; p+=128) s_wh[p]=wh[p];
    __syncthreads();
    int i = blockIdx.x*128 + threadIdx.x;
    if (i >= NB_) return;
    int b = i / N_, n = i % N_;

    // --- node GNN output: sigmoid(agg @ n_w + n_b); zero agg for next step ---
    float ag[30];
    {
        float4* A = &g_agg[i*8];
        #pragma unroll
        for (int q=0;q<7;q++){
            float4 v = A[q];
            ag[4*q]=v.x; ag[4*q+1]=v.y; ag[4*q+2]=v.z; ag[4*q+3]=v.w;
        }
        float4 v = A[7]; ag[28]=v.x; ag[29]=v.y;
        #pragma unroll
        for (int q=0;q<8;q++) A[q]=make_float4(0.f,0.f,0.f,0.f);
    }
    float xc[22];
    #pragma unroll
    for (int c=0;c<13;c++){
        float acc = __ldg(&nb[c]);
        #pragma unroll
        for (int r=0;r<30;r++) acc = fmaf(ag[r], __ldg(&nw[r*13+c]), acc);
        xc[c] = sigm(acc);
    }
    xc[13] = g_xn[i];
    const float* f = feat + ((size_t)(b*FT_ + HIST_ + t)*N_ + n)*8;
    #pragma unroll
    for (int k=0;k<8;k++) xc[14+k]=f[k];

    // --- GRU: coalesced transposed state ---
    float h[64];
    #pragma unroll
    for (int u=0;u<64;u++) h[u] = g_hnT[u*NB_ + i];

    float fcacc = 0.f;
    #pragma unroll 2
    for (int u=0;u<64;u++){
        const float2* wr = (const float2*)(wi + (size_t)u*22);
        const float2* wz = (const float2*)(wi + (size_t)(64+u)*22);
        const float2* wn2= (const float2*)(wi + (size_t)(128+u)*22);
        float gr = __ldg(&bi[u]), gz = __ldg(&bi[64+u]), gn = __ldg(&bi[128+u]);
        #pragma unroll
        for (int k=0;k<11;k++){
            float2 a = __ldg(&wr[k]);  gr = fmaf(a.x,xc[2*k],fmaf(a.y,xc[2*k+1],gr));
            float2 c = __ldg(&wz[k]);  gz = fmaf(c.x,xc[2*k],fmaf(c.y,xc[2*k+1],gz));
            float2 d = __ldg(&wn2[k]); gn = fmaf(d.x,xc[2*k],fmaf(d.y,xc[2*k+1],gn));
        }
        float hr = __ldg(&bh[u]), hz = __ldg(&bh[64+u]), hv_n = __ldg(&bh[128+u]);
        const float4* whr = (const float4*)&s_wh[u*64];
        const float4* whz = (const float4*)&s_wh[(64+u)*64];
        const float4* whn = (const float4*)&s_wh[(128+u)*64];
        #pragma unroll
        for (int k=0;k<16;k++){
            float4 a = whr[k];
            hr = fmaf(a.x,h[4*k],fmaf(a.y,h[4*k+1],fmaf(a.z,h[4*k+2],fmaf(a.w,h[4*k+3],hr))));
            float4 c = whz[k];
            hz = fmaf(c.x,h[4*k],fmaf(c.y,h[4*k+1],fmaf(c.z,h[4*k+2],fmaf(c.w,h[4*k+3],hz))));
            float4 d = whn[k];
            hv_n = fmaf(d.x,h[4*k],fmaf(d.y,h[4*k+1],fmaf(d.z,h[4*k+2],fmaf(d.w,h[4*k+3],hv_n))));
        }
        float r = sigm(gr+hr), z = sigm(gz+hz);
        float nn = tanh_fast(gn + r*hv_n);
        float hv = (1.f-z)*nn + z*h[u];
        g_hnT[u*NB_ + i] = hv;         // coalesced store
        fcacc = fmaf(hv, __ldg(&fw[u]), fcacc);
    }
    float xn = fcacc + __ldg(&fb[0]);
    g_xn[i] = xn;
    out[(size_t)i*PRED_ + t] = xn;

    // --- fused node_pre for step t+1 ---
    if (t+1 < PRED_){
        float x[9];
        x[0] = xn;
        const float* f2 = feat + ((size_t)(b*FT_ + HIST_ + t+1)*N_ + n)*8;
        #pragma unroll
        for (int k=0;k<8;k++) x[1+k]=f2[k];
        float ws0 = fmaxf(__ldg(&ws[0]),1e-6f), ws1 = fmaxf(__ldg(&ws[1]),1e-6f);
        float w0 = fmaxf(x[7]*ws0 + __ldg(&wm[0]), 0.f);
        float wd = (x[8]*ws1 + __ldg(&wm[1])) * 0.017453292519943295f;
        float sw, cw;
        __sincosf(wd, &sw, &cw);
        g_wind[i] = make_float2(w0*cw, w0*sw);
        float ps[32], pt[32];
        #pragma unroll
        for (int j=0;j<32;j++){ ps[j]=0.f; pt[j]=0.f; }
        #pragma unroll
        for (int k=0;k<9;k++){
            float xv = x[k];
            #pragma unroll
            for (int j=0;j<32;j++){
                ps[j] = fmaf(xv, __ldg(&w1[k*32+j]),     ps[j]);
                pt[j] = fmaf(xv, __ldg(&w1[(9+k)*32+j]), pt[j]);
            }
        }
        float4* Pd = &g_Psrc[i*8];
        float4* Td = &g_Ptgt[i*8];
        #pragma unroll
        for (int q=0;q<8;q++){
            Pd[q]=make_float4(ps[4*q],ps[4*q+1],ps[4*q+2],ps[4*q+3]);
            Td[q]=make_float4(pt[4*q],pt[4*q+1],pt[4*q+2],pt[4*q+3]);
        }
    }
}

extern "C" void kernel_launch(void* const* d_in, const int* in_sizes, int n_in,
                              void* d_out, int out_size){
    const float* pm   = (const float*)d_in[0];
    const float* feat = (const float*)d_in[1];
    const float* ea   = (const float*)d_in[2];
    const float* wm   = (const float*)d_in[3];
    const float* ws   = (const float*)d_in[4];
    const float* ew1  = (const float*)d_in[5];
    const float* eb1  = (const float*)d_in[6];
    const float* ew2  = (const float*)d_in[7];
    const float* eb2  = (const float*)d_in[8];
    const float* nw   = (const float*)d_in[9];
    const float* nb   = (const float*)d_in[10];
    const float* wi   = (const float*)d_in[11];
    const float* wh   = (const float*)d_in[12];
    const float* bi   = (const float*)d_in[13];
    const float* bh   = (const float*)d_in[14];
    const float* fw   = (const float*)d_in[15];
    const float* fb   = (const float*)d_in[16];
    const void*  ei   = d_in[17];
    float* out = (float*)d_out;

    dim3 ge(E_/128, B_);   // 1250 CTAs x 8 warps x 16 edges = 160k edges
    k_detect<<<64,256>>>((const unsigned*)ei);
    k_stats<<<1,1024>>>(ea);
    k_setup<<<CE_BLOCKS + (NB_+255)/256, 256>>>(pm, feat, ea, ew1, eb1, wm, ws);
    for (int t=0;t<PRED_;t++){
        k_edge<<<ge,256>>>(ei, ew1, ew2, eb2);
        k_gru<<<(NB_+127)/128,128>>>(feat, nw, nb, wi, wh, bi, bh, fw, fb,
                                     ew1, wm, ws, out, t);
    }
    (void)in_sizes; (void)n_in; (void)out_size;
}